// round 1
// baseline (speedup 1.0000x reference)
#include <cuda_runtime.h>
#include <math.h>

#define CC   256
#define HWD  4096      // 64*64
#define NB   2

// ---------------- scratch (static device globals; no allocation) ------------
__device__ float d_bsf[NB * CC * HWD];                    // 8.4 MB  [n][c][hw]
__device__ float d_T  [NB * CC * HWD];                    // theta   [n][c][hw]
__device__ float d_P  [NB * CC * HWD];                    // phi     [n][c][hw]
__device__ float d_G  [NB * CC * HWD];                    // g       [n][c][hw]
__device__ float d_S  [(size_t)NB * HWD * HWD];           // 134 MB  [n][q][k]
__device__ float d_Y  [NB * HWD * CC];                    // 8.4 MB  [n][q][c]
__device__ float d_OB [NB * CC * HWD];                    // 8.4 MB  [n][c][hw]

// ---------------- gather: bsf = mean of 4 resampled levels ------------------
__global__ void k_bsf(const float* __restrict__ x0, const float* __restrict__ x1,
                      const float* __restrict__ x2, const float* __restrict__ x3) {
    int idx = blockIdx.x * blockDim.x + threadIdx.x;
    if (idx >= NB * CC * HWD) return;
    int xq = idx & 63;
    int yq = (idx >> 6) & 63;
    int nc = idx >> 12;                       // 0..511  (n*C + c)
    const float* p0 = x0 + (size_t)nc * 128 * 128;
    int y2 = yq * 2, x2i = xq * 2;
    float m = fmaxf(fmaxf(p0[y2 * 128 + x2i],       p0[y2 * 128 + x2i + 1]),
                    fmaxf(p0[(y2 + 1) * 128 + x2i], p0[(y2 + 1) * 128 + x2i + 1]));
    float f1 = x1[(size_t)nc * 4096 + yq * 64 + xq];
    float f2 = x2[(size_t)nc * 1024 + (yq >> 1) * 32 + (xq >> 1)];
    float f3 = x3[(size_t)nc * 256  + (yq >> 2) * 16 + (xq >> 2)];
    d_bsf[idx] = 0.25f * (m + f1 + f2 + f3);
}

// ---------------- shared GEMM microkernel (128x128x8, 256 thr, 8x8) ---------
__device__ __forceinline__ void mm_step(const float (*As)[128], const float (*Bs)[128],
                                        float acc[8][8], int tx, int ty) {
#pragma unroll
    for (int kk = 0; kk < 8; ++kk) {
        float a[8], b[8];
#pragma unroll
        for (int i = 0; i < 8; ++i) a[i] = As[kk][ty * 8 + i];
#pragma unroll
        for (int j = 0; j < 8; ++j) b[j] = Bs[kk][tx * 8 + j];
#pragma unroll
        for (int i = 0; i < 8; ++i)
#pragma unroll
            for (int j = 0; j < 8; ++j)
                acc[i][j] += a[i] * b[j];
    }
}

// ---------------- conv1x1 x3: theta/phi/g from bsf --------------------------
// out[co][q] = sum_ci W[co][ci] * bsf[ci][q] + bias[co]
__global__ __launch_bounds__(256, 2)
void k_conv3(const float* __restrict__ gw, const float* __restrict__ gb,
             const float* __restrict__ tw, const float* __restrict__ tb,
             const float* __restrict__ pw, const float* __restrict__ pb) {
    int b     = blockIdx.z / 3;
    int which = blockIdx.z % 3;
    const float* W; const float* bias; float* dst;
    if (which == 0)      { W = tw; bias = tb; dst = d_T; }
    else if (which == 1) { W = pw; bias = pb; dst = d_P; }
    else                 { W = gw; bias = gb; dst = d_G; }
    const float* B = d_bsf + (size_t)b * CC * HWD;
    dst += (size_t)b * CC * HWD;

    int m0 = blockIdx.y * 128, n0 = blockIdx.x * 128;
    __shared__ float As[8][128], Bs[8][128];
    int tid = threadIdx.x;
    int tx = tid & 15, ty = tid >> 4;
    float acc[8][8];
#pragma unroll
    for (int i = 0; i < 8; ++i)
#pragma unroll
        for (int j = 0; j < 8; ++j) acc[i][j] = 0.f;

    int a_x  = tid >> 1;            // m within tile
    int a_k4 = (tid & 1) * 4;       // k quad
    int b_k  = tid >> 5;            // k row
    int b_n  = (tid & 31) * 4;      // n quad

    for (int k0 = 0; k0 < CC; k0 += 8) {
        float4 av = *(const float4*)&W[(size_t)(m0 + a_x) * CC + k0 + a_k4];
        As[a_k4 + 0][a_x] = av.x; As[a_k4 + 1][a_x] = av.y;
        As[a_k4 + 2][a_x] = av.z; As[a_k4 + 3][a_x] = av.w;
        *(float4*)&Bs[b_k][b_n] = *(const float4*)&B[(size_t)(k0 + b_k) * HWD + n0 + b_n];
        __syncthreads();
        mm_step(As, Bs, acc, tx, ty);
        __syncthreads();
    }
#pragma unroll
    for (int i = 0; i < 8; ++i) {
        int row = m0 + ty * 8 + i;
        float bi = bias[row];
        float* o = dst + (size_t)row * HWD + n0 + tx * 8;
#pragma unroll
        for (int j = 0; j < 8; ++j) o[j] = acc[i][j] + bi;
    }
}

// ---------------- scores: S[q][k] = sum_c T[c][q] * P[c][k] -----------------
__global__ __launch_bounds__(256, 2)
void k_scores() {
    int b = blockIdx.z;
    const float* A  = d_T + (size_t)b * CC * HWD;   // [k=c][m=q]
    const float* Bm = d_P + (size_t)b * CC * HWD;   // [k=c][n=k]
    float* Cp = d_S + (size_t)b * HWD * HWD;

    int m0 = blockIdx.y * 128, n0 = blockIdx.x * 128;
    __shared__ float As[8][128], Bs[8][128];
    int tid = threadIdx.x;
    int tx = tid & 15, ty = tid >> 4;
    float acc[8][8];
#pragma unroll
    for (int i = 0; i < 8; ++i)
#pragma unroll
        for (int j = 0; j < 8; ++j) acc[i][j] = 0.f;

    int l_k = tid >> 5;
    int l_x = (tid & 31) * 4;

    for (int k0 = 0; k0 < CC; k0 += 8) {
        *(float4*)&As[l_k][l_x] = *(const float4*)&A [(size_t)(k0 + l_k) * HWD + m0 + l_x];
        *(float4*)&Bs[l_k][l_x] = *(const float4*)&Bm[(size_t)(k0 + l_k) * HWD + n0 + l_x];
        __syncthreads();
        mm_step(As, Bs, acc, tx, ty);
        __syncthreads();
    }
#pragma unroll
    for (int i = 0; i < 8; ++i) {
        float* o = Cp + (size_t)(m0 + ty * 8 + i) * HWD + n0 + tx * 8;
#pragma unroll
        for (int j = 0; j < 8; ++j) o[j] = acc[i][j];
    }
}

// ---------------- row softmax over S ----------------------------------------
__global__ void k_softmax() {
    int r = blockIdx.x;                          // 0..NB*HWD-1
    float* row = d_S + (size_t)r * HWD;
    int t = threadIdx.x;                         // 256 threads
    float v[16];
    float mx = -3.4e38f;
#pragma unroll
    for (int i = 0; i < 16; ++i) {
        v[i] = row[i * 256 + t];
        mx = fmaxf(mx, v[i]);
    }
    __shared__ float red[256];
    red[t] = mx; __syncthreads();
    for (int s = 128; s > 0; s >>= 1) {
        if (t < s) red[t] = fmaxf(red[t], red[t + s]);
        __syncthreads();
    }
    mx = red[0]; __syncthreads();
    float sum = 0.f;
#pragma unroll
    for (int i = 0; i < 16; ++i) {
        v[i] = expf(v[i] - mx);
        sum += v[i];
    }
    red[t] = sum; __syncthreads();
    for (int s = 128; s > 0; s >>= 1) {
        if (t < s) red[t] += red[t + s];
        __syncthreads();
    }
    float inv = 1.f / red[0];
#pragma unroll
    for (int i = 0; i < 16; ++i) row[i * 256 + t] = v[i] * inv;
}

// ---------------- y: Y[q][c] = sum_k S[q][k] * G[c][k] ----------------------
__global__ __launch_bounds__(256, 2)
void k_gemm_y() {
    int b = blockIdx.z;
    const float* A  = d_S + (size_t)b * HWD * HWD;  // [m=q][k], ld HWD
    const float* Bm = d_G + (size_t)b * CC * HWD;   // [n=c][k], ld HWD
    float* Cp = d_Y + (size_t)b * HWD * CC;

    int m0 = blockIdx.y * 128, n0 = blockIdx.x * 128;
    __shared__ float As[8][128], Bs[8][128];
    int tid = threadIdx.x;
    int tx = tid & 15, ty = tid >> 4;
    float acc[8][8];
#pragma unroll
    for (int i = 0; i < 8; ++i)
#pragma unroll
        for (int j = 0; j < 8; ++j) acc[i][j] = 0.f;

    int lx  = tid >> 1;
    int lk4 = (tid & 1) * 4;

    for (int k0 = 0; k0 < HWD; k0 += 8) {
        float4 av = *(const float4*)&A [(size_t)(m0 + lx) * HWD + k0 + lk4];
        As[lk4 + 0][lx] = av.x; As[lk4 + 1][lx] = av.y;
        As[lk4 + 2][lx] = av.z; As[lk4 + 3][lx] = av.w;
        float4 bv = *(const float4*)&Bm[(size_t)(n0 + lx) * HWD + k0 + lk4];
        Bs[lk4 + 0][lx] = bv.x; Bs[lk4 + 1][lx] = bv.y;
        Bs[lk4 + 2][lx] = bv.z; Bs[lk4 + 3][lx] = bv.w;
        __syncthreads();
        mm_step(As, Bs, acc, tx, ty);
        __syncthreads();
    }
#pragma unroll
    for (int i = 0; i < 8; ++i) {
        float* o = Cp + (size_t)(m0 + ty * 8 + i) * CC + n0 + tx * 8;
#pragma unroll
        for (int j = 0; j < 8; ++j) o[j] = acc[i][j];
    }
}

// ---------------- out conv + residual: OB = bsf + conv_out(y) ---------------
// OB[c][q] = bsf[c][q] + sum_i W[c][i] * Y[q][i] + bias[c]
__global__ __launch_bounds__(256, 2)
void k_gemm_out(const float* __restrict__ ow, const float* __restrict__ ob) {
    int b = blockIdx.z;
    const float* A  = ow;                            // [m=c][k=i], ld CC
    const float* Bm = d_Y + (size_t)b * HWD * CC;    // [n=q][k=i], ld CC
    const float* bsfp = d_bsf + (size_t)b * CC * HWD;
    float* Cp = d_OB + (size_t)b * CC * HWD;

    int m0 = blockIdx.y * 128, n0 = blockIdx.x * 128;
    __shared__ float As[8][128], Bs[8][128];
    int tid = threadIdx.x;
    int tx = tid & 15, ty = tid >> 4;
    float acc[8][8];
#pragma unroll
    for (int i = 0; i < 8; ++i)
#pragma unroll
        for (int j = 0; j < 8; ++j) acc[i][j] = 0.f;

    int lx  = tid >> 1;
    int lk4 = (tid & 1) * 4;

    for (int k0 = 0; k0 < CC; k0 += 8) {
        float4 av = *(const float4*)&A [(size_t)(m0 + lx) * CC + k0 + lk4];
        As[lk4 + 0][lx] = av.x; As[lk4 + 1][lx] = av.y;
        As[lk4 + 2][lx] = av.z; As[lk4 + 3][lx] = av.w;
        float4 bv = *(const float4*)&Bm[(size_t)(n0 + lx) * CC + k0 + lk4];
        Bs[lk4 + 0][lx] = bv.x; Bs[lk4 + 1][lx] = bv.y;
        Bs[lk4 + 2][lx] = bv.z; Bs[lk4 + 3][lx] = bv.w;
        __syncthreads();
        mm_step(As, Bs, acc, tx, ty);
        __syncthreads();
    }
#pragma unroll
    for (int i = 0; i < 8; ++i) {
        int row = m0 + ty * 8 + i;
        float bi = ob[row];
        const float* bp = bsfp + (size_t)row * HWD + n0 + tx * 8;
        float* o = Cp + (size_t)row * HWD + n0 + tx * 8;
#pragma unroll
        for (int j = 0; j < 8; ++j) o[j] = acc[i][j] + bi + bp[j];
    }
}

// ---------------- scatter: four residual outputs ----------------------------
__global__ void k_out0(const float* __restrict__ x0, float* __restrict__ out) {
    int idx = blockIdx.x * blockDim.x + threadIdx.x;      // NB*CC*128*128
    if (idx >= NB * CC * 128 * 128) return;
    int x = idx & 127, y = (idx >> 7) & 127, nc = idx >> 14;
    out[idx] = d_OB[(size_t)nc * 4096 + (y >> 1) * 64 + (x >> 1)] + x0[idx];
}
__global__ void k_out1(const float* __restrict__ x1, float* __restrict__ out) {
    int idx = blockIdx.x * blockDim.x + threadIdx.x;      // NB*CC*4096
    if (idx >= NB * CC * HWD) return;
    out[idx] = d_OB[idx] + x1[idx];
}
__global__ void k_out2(const float* __restrict__ x2, float* __restrict__ out) {
    int idx = blockIdx.x * blockDim.x + threadIdx.x;      // NB*CC*1024
    if (idx >= NB * CC * 1024) return;
    int x = idx & 31, y = (idx >> 5) & 31, nc = idx >> 10;
    const float* p = d_OB + (size_t)nc * 4096 + (y * 2) * 64 + x * 2;
    float m = fmaxf(fmaxf(p[0], p[1]), fmaxf(p[64], p[65]));
    out[idx] = m + x2[idx];
}
__global__ void k_out3(const float* __restrict__ x3, float* __restrict__ out) {
    int idx = blockIdx.x * blockDim.x + threadIdx.x;      // NB*CC*256
    if (idx >= NB * CC * 256) return;
    int x = idx & 15, y = (idx >> 4) & 15, nc = idx >> 8;
    const float* p = d_OB + (size_t)nc * 4096 + (y * 4) * 64 + x * 4;
    float m = -3.4e38f;
#pragma unroll
    for (int r = 0; r < 4; ++r)
#pragma unroll
        for (int c = 0; c < 4; ++c) m = fmaxf(m, p[r * 64 + c]);
    out[idx] = m + x3[idx];
}

// ---------------- launch -----------------------------------------------------
extern "C" void kernel_launch(void* const* d_in, const int* in_sizes, int n_in,
                              void* d_out, int out_size) {
    const float* x0 = (const float*)d_in[0];
    const float* x1 = (const float*)d_in[1];
    const float* x2 = (const float*)d_in[2];
    const float* x3 = (const float*)d_in[3];
    const float* g_w = (const float*)d_in[4];
    const float* g_b = (const float*)d_in[5];
    const float* t_w = (const float*)d_in[6];
    const float* t_b = (const float*)d_in[7];
    const float* p_w = (const float*)d_in[8];
    const float* p_b = (const float*)d_in[9];
    const float* o_w = (const float*)d_in[10];
    const float* o_b = (const float*)d_in[11];
    float* out = (float*)d_out;

    // 1. gather -> bsf
    k_bsf<<<(NB * CC * HWD + 255) / 256, 256>>>(x0, x1, x2, x3);

    // 2. theta/phi/g conv1x1
    {
        dim3 g(HWD / 128, CC / 128, NB * 3);
        k_conv3<<<g, 256>>>(g_w, g_b, t_w, t_b, p_w, p_b);
    }

    // 3. attention scores
    {
        dim3 g(HWD / 128, HWD / 128, NB);
        k_scores<<<g, 256>>>();
    }

    // 4. softmax rows
    k_softmax<<<NB * HWD, 256>>>();

    // 5. y = S @ G^T
    {
        dim3 g(CC / 128, HWD / 128, NB);
        k_gemm_y<<<g, 256>>>();
    }

    // 6. out conv + residual add -> OB
    {
        dim3 g(HWD / 128, CC / 128, NB);
        k_gemm_out<<<g, 256>>>(o_w, o_b);
    }

    // 7. scatter outputs
    float* o0 = out;
    float* o1 = o0 + (size_t)NB * CC * 128 * 128;
    float* o2 = o1 + (size_t)NB * CC * 64 * 64;
    float* o3 = o2 + (size_t)NB * CC * 32 * 32;
    k_out0<<<(NB * CC * 128 * 128 + 255) / 256, 256>>>(x0, o0);
    k_out1<<<(NB * CC * HWD + 255) / 256, 256>>>(x1, o1);
    k_out2<<<(NB * CC * 1024 + 255) / 256, 256>>>(x2, o2);
    k_out3<<<(NB * CC * 256 + 255) / 256, 256>>>(x3, o3);
}

// round 3
// speedup vs baseline: 4.9715x; 4.9715x over previous
#include <cuda_runtime.h>
#include <cuda_bf16.h>
#include <cstdint>
#include <math.h>

#define CC   256
#define HWD  4096
#define NB   2

using bf16 = __nv_bfloat16;

// ------------------------------ scratch -------------------------------------
__device__ __align__(1024) float d_bsf [NB * CC * HWD];            // [b][c][hw] fp32
__device__ __align__(1024) bf16  d_bsfT[NB * HWD * CC];            // [b][hw][c]
__device__ __align__(1024) bf16  d_Wb  [4 * CC * CC];              // theta,phi,g,out
__device__ __align__(1024) bf16  d_T2  [NB * HWD * CC];            // [b][q][c]
__device__ __align__(1024) bf16  d_P2  [NB * HWD * CC];            // [b][k][c]
__device__ __align__(1024) bf16  d_GB  [NB * CC * HWD];            // [b][c][k]
__device__ __align__(1024) bf16  d_SB  [(size_t)NB * HWD * HWD];   // [b][q][k]
__device__ __align__(1024) bf16  d_Yb  [NB * HWD * CC];            // [b][q][c]
__device__ __align__(1024) float d_OB  [NB * CC * HWD];            // [b][c][hw] fp32

// ------------------------------ helpers -------------------------------------
__device__ __forceinline__ uint32_t s2u(const void* p) {
    uint32_t a;
    asm("{ .reg .u64 t; cvta.to.shared.u64 t, %1; cvt.u32.u64 %0, t; }"
        : "=r"(a) : "l"(p));
    return a;
}
__device__ __forceinline__ void cp16(uint32_t dst, const void* src) {
    asm volatile("cp.async.cg.shared.global [%0], [%1], 16;" :: "r"(dst), "l"(src));
}
#define CP_COMMIT() asm volatile("cp.async.commit_group;" ::: "memory")

__device__ __forceinline__ void ldsm4(uint32_t& r0, uint32_t& r1,
                                      uint32_t& r2, uint32_t& r3, uint32_t a) {
    asm volatile("ldmatrix.sync.aligned.m8n8.x4.shared.b16 {%0,%1,%2,%3}, [%4];"
                 : "=r"(r0), "=r"(r1), "=r"(r2), "=r"(r3) : "r"(a));
}
__device__ __forceinline__ void mma16816(float* c, const uint32_t* a,
                                         uint32_t b0, uint32_t b1) {
    asm volatile(
        "mma.sync.aligned.m16n8k16.row.col.f32.bf16.bf16.f32 "
        "{%0,%1,%2,%3}, {%4,%5,%6,%7}, {%8,%9}, {%0,%1,%2,%3};"
        : "+f"(c[0]), "+f"(c[1]), "+f"(c[2]), "+f"(c[3])
        : "r"(a[0]), "r"(a[1]), "r"(a[2]), "r"(a[3]), "r"(b0), "r"(b1));
}

// ------------------------- bf16 TN GEMM (mma.sync) ---------------------------
// C[M,N] = A[M,K] * B[N,K]^T, A/B bf16 K-major. Block 128x128xK32, 256 thr.
// MODE 0: bf16 C, bias[col]   (theta/phi)
// MODE 1: bf16 C, bias[row]   (g)
// MODE 2: bf16 C, no bias     (scores, y)
// MODE 3: fp32 C, bias[row] + bsf add (out conv)
#define ROWB   80
#define STAGEB (128 * ROWB)          // 10240 bytes per operand per stage
#define NSTAGE 3
#define GEMM_SMEM (NSTAGE * 2 * STAGEB)  // 61440

template<int MODE>
__global__ __launch_bounds__(256, 2)
void k_gemm(const bf16* __restrict__ Ag, const bf16* __restrict__ Bg,
            void* __restrict__ Cg, int ldA, int ldB, int ldC, int K,
            long long strA, long long strB, long long strC,
            const float* __restrict__ bias,
            const float* __restrict__ bsf, long long strBsf) {
    extern __shared__ char sm[];
    const int tid = threadIdx.x;
    const int wid = tid >> 5, lane = tid & 31;
    const int bz = blockIdx.z;
    const int n0 = blockIdx.x * 128, m0 = blockIdx.y * 128;
    const char* Ab = (const char*)(Ag + (size_t)bz * strA + (size_t)m0 * ldA);
    const char* Bb = (const char*)(Bg + (size_t)bz * strB + (size_t)n0 * ldB);
    const uint32_t sbase = s2u(sm);
    const int warpM = wid & 3, warpN = wid >> 2;
    const long lA2 = (long)ldA * 2, lB2 = (long)ldB * 2;

    float acc[2][8][4];
#pragma unroll
    for (int mt = 0; mt < 2; ++mt)
#pragma unroll
        for (int nt = 0; nt < 8; ++nt)
#pragma unroll
            for (int e = 0; e < 4; ++e) acc[mt][nt][e] = 0.f;

    const int KT = K >> 5;

    auto load_stage = [&](int kt, int slot) {
        uint32_t dA = sbase + slot * (2 * STAGEB);
        uint32_t dB = dA + STAGEB;
        long koff = (long)kt * 64;
#pragma unroll
        for (int rep = 0; rep < 2; ++rep) {
            int task = rep * 256 + tid;       // 0..511
            int row = task >> 2, ch = task & 3;
            cp16(dA + row * ROWB + ch * 16, Ab + (long)row * lA2 + koff + ch * 16);
            cp16(dB + row * ROWB + ch * 16, Bb + (long)row * lB2 + koff + ch * 16);
        }
    };

    auto compute = [&](int slot) {
        uint32_t bA = sbase + slot * (2 * STAGEB);
        uint32_t bB = bA + STAGEB;
#pragma unroll
        for (int ks = 0; ks < 2; ++ks) {
            uint32_t a[2][4];
#pragma unroll
            for (int mt = 0; mt < 2; ++mt) {
                int row = warpM * 32 + mt * 16 + (lane & 15);
                ldsm4(a[mt][0], a[mt][1], a[mt][2], a[mt][3],
                      bA + row * ROWB + ks * 32 + ((lane >> 4) << 4));
            }
#pragma unroll
            for (int np = 0; np < 4; ++np) {
                int nrow = warpN * 64 + np * 16 + (lane & 7) + ((lane >> 4) << 3);
                uint32_t b0, b1, b2, b3;
                ldsm4(b0, b1, b2, b3,
                      bB + nrow * ROWB + ks * 32 + (((lane >> 3) & 1) << 4));
#pragma unroll
                for (int mt = 0; mt < 2; ++mt) {
                    mma16816(acc[mt][np * 2 + 0], a[mt], b0, b1);
                    mma16816(acc[mt][np * 2 + 1], a[mt], b2, b3);
                }
            }
        }
    };

    load_stage(0, 0); CP_COMMIT();
    load_stage(1, 1); CP_COMMIT();
    for (int kt = 0; kt < KT; ++kt) {
        if (kt + 2 < KT) load_stage(kt + 2, (kt + 2) % NSTAGE);
        CP_COMMIT();
        asm volatile("cp.async.wait_group 2;" ::: "memory");
        __syncthreads();
        compute(kt % NSTAGE);
        __syncthreads();
    }

    // ---------------- epilogue ----------------
    const int mrow = m0 + warpM * 32 + (lane >> 2);
    const int ncol = n0 + warpN * 64 + ((lane & 3) << 1);
#pragma unroll
    for (int mt = 0; mt < 2; ++mt) {
        int r = mrow + mt * 16;
        float br0 = 0.f, br8 = 0.f;
        if (MODE == 1 || MODE == 3) { br0 = bias[r]; br8 = bias[r + 8]; }
#pragma unroll
        for (int nt = 0; nt < 8; ++nt) {
            int c = ncol + nt * 8;
            float v0 = acc[mt][nt][0], v1 = acc[mt][nt][1];
            float v2 = acc[mt][nt][2], v3 = acc[mt][nt][3];
            if (MODE == 0) {
                float bc0 = bias[c], bc1 = bias[c + 1];
                v0 += bc0; v1 += bc1; v2 += bc0; v3 += bc1;
            } else if (MODE == 1) {
                v0 += br0; v1 += br0; v2 += br8; v3 += br8;
            }
            if (MODE == 3) {
                float* C = (float*)Cg + (size_t)blockIdx.z * strC;
                const float* bs = bsf + (size_t)blockIdx.z * strBsf;
                float2 lo = *(const float2*)(bs + (size_t)r * ldC + c);
                float2 hi = *(const float2*)(bs + (size_t)(r + 8) * ldC + c);
                float2 o0 = make_float2(v0 + br0 + lo.x, v1 + br0 + lo.y);
                float2 o1 = make_float2(v2 + br8 + hi.x, v3 + br8 + hi.y);
                *(float2*)(C + (size_t)r * ldC + c) = o0;
                *(float2*)(C + (size_t)(r + 8) * ldC + c) = o1;
            } else {
                bf16* C = (bf16*)Cg + (size_t)blockIdx.z * strC;
                *(__nv_bfloat162*)(C + (size_t)r * ldC + c) =
                    __floats2bfloat162_rn(v0, v1);
                *(__nv_bfloat162*)(C + (size_t)(r + 8) * ldC + c) =
                    __floats2bfloat162_rn(v2, v3);
            }
        }
    }
}

// ---------------------------- elementwise ------------------------------------
__global__ void k_wcvt(const float* __restrict__ tw, const float* __restrict__ pw,
                       const float* __restrict__ gw, const float* __restrict__ ow) {
    int i = blockIdx.x * blockDim.x + threadIdx.x;
    if (i >= CC * CC) return;
    d_Wb[0 * CC * CC + i] = __float2bfloat16(tw[i]);
    d_Wb[1 * CC * CC + i] = __float2bfloat16(pw[i]);
    d_Wb[2 * CC * CC + i] = __float2bfloat16(gw[i]);
    d_Wb[3 * CC * CC + i] = __float2bfloat16(ow[i]);
}

__global__ void k_bsf(const float* __restrict__ x0, const float* __restrict__ x1,
                      const float* __restrict__ x2, const float* __restrict__ x3) {
    int idx = blockIdx.x * blockDim.x + threadIdx.x;
    if (idx >= NB * CC * HWD) return;
    int xq = idx & 63, yq = (idx >> 6) & 63, nc = idx >> 12;
    const float* p0 = x0 + (size_t)nc * 128 * 128;
    int y2 = yq * 2, x2i = xq * 2;
    float m = fmaxf(fmaxf(p0[y2 * 128 + x2i],       p0[y2 * 128 + x2i + 1]),
                    fmaxf(p0[(y2 + 1) * 128 + x2i], p0[(y2 + 1) * 128 + x2i + 1]));
    float f1 = x1[(size_t)nc * 4096 + yq * 64 + xq];
    float f2 = x2[(size_t)nc * 1024 + (yq >> 1) * 32 + (xq >> 1)];
    float f3 = x3[(size_t)nc * 256  + (yq >> 2) * 16 + (xq >> 2)];
    d_bsf[idx] = 0.25f * (m + f1 + f2 + f3);
}

__global__ void k_transpose() {              // bsf fp32 [c][hw] -> bsfT bf16 [hw][c]
    __shared__ float t[32][33];
    int b = blockIdx.z;
    int hw0 = blockIdx.x * 32, c0 = blockIdx.y * 32;
    for (int i = threadIdx.y; i < 32; i += 8)
        t[i][threadIdx.x] = d_bsf[((long)b * CC + c0 + i) * HWD + hw0 + threadIdx.x];
    __syncthreads();
    for (int i = threadIdx.y; i < 32; i += 8)
        d_bsfT[((long)b * HWD + hw0 + i) * CC + c0 + threadIdx.x] =
            __float2bfloat16(t[threadIdx.x][i]);
}

__global__ void k_softmax() {                // in-place bf16 row softmax
    size_t r = blockIdx.x;
    uint32_t* row = (uint32_t*)(d_SB + r * HWD);    // 2048 u32 (bf16x2)
    int t = threadIdx.x;
    float v[16];
    float mx = -3.4e38f;
#pragma unroll
    for (int i = 0; i < 8; ++i) {
        uint32_t u = row[i * 256 + t];
        __nv_bfloat162 h = *(__nv_bfloat162*)&u;
        v[2 * i]     = __bfloat162float(h.x);
        v[2 * i + 1] = __bfloat162float(h.y);
        mx = fmaxf(mx, fmaxf(v[2 * i], v[2 * i + 1]));
    }
    __shared__ float red[256];
    red[t] = mx; __syncthreads();
    for (int s = 128; s > 0; s >>= 1) {
        if (t < s) red[t] = fmaxf(red[t], red[t + s]);
        __syncthreads();
    }
    mx = red[0]; __syncthreads();
    float sum = 0.f;
#pragma unroll
    for (int i = 0; i < 16; ++i) { v[i] = expf(v[i] - mx); sum += v[i]; }
    red[t] = sum; __syncthreads();
    for (int s = 128; s > 0; s >>= 1) {
        if (t < s) red[t] += red[t + s];
        __syncthreads();
    }
    float inv = 1.f / red[0];
#pragma unroll
    for (int i = 0; i < 8; ++i) {
        __nv_bfloat162 h = __floats2bfloat162_rn(v[2 * i] * inv, v[2 * i + 1] * inv);
        row[i * 256 + t] = *(uint32_t*)&h;
    }
}

__global__ void k_out0(const float* __restrict__ x0, float* __restrict__ out) {
    int idx = blockIdx.x * blockDim.x + threadIdx.x;
    if (idx >= NB * CC * 128 * 128) return;
    int x = idx & 127, y = (idx >> 7) & 127, nc = idx >> 14;
    out[idx] = d_OB[(size_t)nc * 4096 + (y >> 1) * 64 + (x >> 1)] + x0[idx];
}
__global__ void k_out1(const float* __restrict__ x1, float* __restrict__ out) {
    int idx = blockIdx.x * blockDim.x + threadIdx.x;
    if (idx >= NB * CC * HWD) return;
    out[idx] = d_OB[idx] + x1[idx];
}
__global__ void k_out2(const float* __restrict__ x2, float* __restrict__ out) {
    int idx = blockIdx.x * blockDim.x + threadIdx.x;
    if (idx >= NB * CC * 1024) return;
    int x = idx & 31, y = (idx >> 5) & 31, nc = idx >> 10;
    const float* p = d_OB + (size_t)nc * 4096 + (y * 2) * 64 + x * 2;
    float m = fmaxf(fmaxf(p[0], p[1]), fmaxf(p[64], p[65]));
    out[idx] = m + x2[idx];
}
__global__ void k_out3(const float* __restrict__ x3, float* __restrict__ out) {
    int idx = blockIdx.x * blockDim.x + threadIdx.x;
    if (idx >= NB * CC * 256) return;
    int x = idx & 15, y = (idx >> 4) & 15, nc = idx >> 8;
    const float* p = d_OB + (size_t)nc * 4096 + (y * 4) * 64 + x * 4;
    float m = -3.4e38f;
#pragma unroll
    for (int r = 0; r < 4; ++r)
#pragma unroll
        for (int c = 0; c < 4; ++c) m = fmaxf(m, p[r * 64 + c]);
    out[idx] = m + x3[idx];
}

// ------------------------------ launch ---------------------------------------
extern "C" void kernel_launch(void* const* d_in, const int* in_sizes, int n_in,
                              void* d_out, int out_size) {
    const float* x0 = (const float*)d_in[0];
    const float* x1 = (const float*)d_in[1];
    const float* x2 = (const float*)d_in[2];
    const float* x3 = (const float*)d_in[3];
    const float* g_w = (const float*)d_in[4];
    const float* g_b = (const float*)d_in[5];
    const float* t_w = (const float*)d_in[6];
    const float* t_b = (const float*)d_in[7];
    const float* p_w = (const float*)d_in[8];
    const float* p_b = (const float*)d_in[9];
    const float* o_w = (const float*)d_in[10];
    const float* o_b = (const float*)d_in[11];
    float* out = (float*)d_out;

    cudaFuncSetAttribute(k_gemm<0>, cudaFuncAttributeMaxDynamicSharedMemorySize, GEMM_SMEM);
    cudaFuncSetAttribute(k_gemm<1>, cudaFuncAttributeMaxDynamicSharedMemorySize, GEMM_SMEM);
    cudaFuncSetAttribute(k_gemm<2>, cudaFuncAttributeMaxDynamicSharedMemorySize, GEMM_SMEM);
    cudaFuncSetAttribute(k_gemm<3>, cudaFuncAttributeMaxDynamicSharedMemorySize, GEMM_SMEM);

    bf16* ptrW;  cudaGetSymbolAddress((void**)&ptrW,  d_Wb);
    bf16* ptrBT; cudaGetSymbolAddress((void**)&ptrBT, d_bsfT);
    bf16* ptrT;  cudaGetSymbolAddress((void**)&ptrT,  d_T2);
    bf16* ptrP;  cudaGetSymbolAddress((void**)&ptrP,  d_P2);
    bf16* ptrG;  cudaGetSymbolAddress((void**)&ptrG,  d_GB);
    bf16* ptrS;  cudaGetSymbolAddress((void**)&ptrS,  d_SB);
    bf16* ptrY;  cudaGetSymbolAddress((void**)&ptrY,  d_Yb);
    float* ptrB; cudaGetSymbolAddress((void**)&ptrB,  d_bsf);
    float* ptrO; cudaGetSymbolAddress((void**)&ptrO,  d_OB);

    k_wcvt<<<(CC * CC + 255) / 256, 256>>>(t_w, p_w, g_w, o_w);
    k_bsf<<<(NB * CC * HWD + 255) / 256, 256>>>(x0, x1, x2, x3);
    {
        dim3 g(HWD / 32, CC / 32, NB);
        k_transpose<<<g, dim3(32, 8)>>>();
    }
    // theta: C[q][co] = bsfT * Wt^T
    {
        dim3 g(CC / 128, HWD / 128, NB);
        k_gemm<0><<<g, 256, GEMM_SMEM>>>(ptrBT, ptrW + 0 * CC * CC, ptrT,
                                         CC, CC, CC, CC,
                                         (long long)HWD * CC, 0, (long long)HWD * CC,
                                         t_b, nullptr, 0);
        k_gemm<0><<<g, 256, GEMM_SMEM>>>(ptrBT, ptrW + 1 * CC * CC, ptrP,
                                         CC, CC, CC, CC,
                                         (long long)HWD * CC, 0, (long long)HWD * CC,
                                         p_b, nullptr, 0);
    }
    // g: C[co][k] = Wg * bsfT^T
    {
        dim3 g(HWD / 128, CC / 128, NB);
        k_gemm<1><<<g, 256, GEMM_SMEM>>>(ptrW + 2 * CC * CC, ptrBT, ptrG,
                                         CC, CC, HWD, CC,
                                         0, (long long)HWD * CC, (long long)CC * HWD,
                                         g_b, nullptr, 0);
    }
    // scores: C[q][k] = T2 * P2^T
    {
        dim3 g(HWD / 128, HWD / 128, NB);
        k_gemm<2><<<g, 256, GEMM_SMEM>>>(ptrT, ptrP, ptrS,
                                         CC, CC, HWD, CC,
                                         (long long)HWD * CC, (long long)HWD * CC,
                                         (long long)HWD * HWD,
                                         nullptr, nullptr, 0);
    }
    k_softmax<<<NB * HWD, 256>>>();
    // y: C[q][c] = SB * GB^T
    {
        dim3 g(CC / 128, HWD / 128, NB);
        k_gemm<2><<<g, 256, GEMM_SMEM>>>(ptrS, ptrG, ptrY,
                                         HWD, HWD, CC, HWD,
                                         (long long)HWD * HWD, (long long)CC * HWD,
                                         (long long)HWD * CC,
                                         nullptr, nullptr, 0);
    }
    // out conv: C[co][q] = Wo * Yb^T + bias + bsf
    {
        dim3 g(HWD / 128, CC / 128, NB);
        k_gemm<3><<<g, 256, GEMM_SMEM>>>(ptrW + 3 * CC * CC, ptrY, ptrO,
                                         CC, CC, HWD, CC,
                                         0, (long long)HWD * CC, (long long)CC * HWD,
                                         o_b, ptrB, (long long)CC * HWD);
    }
    float* o0 = out;
    float* o1 = o0 + (size_t)NB * CC * 128 * 128;
    float* o2 = o1 + (size_t)NB * CC * 64 * 64;
    float* o3 = o2 + (size_t)NB * CC * 32 * 32;
    k_out0<<<(NB * CC * 128 * 128 + 255) / 256, 256>>>(x0, o0);
    k_out1<<<(NB * CC * HWD + 255) / 256, 256>>>(x1, o1);
    k_out2<<<(NB * CC * 1024 + 255) / 256, 256>>>(x2, o2);
    k_out3<<<(NB * CC * 256 + 255) / 256, 256>>>(x3, o3);
}

// round 4
// speedup vs baseline: 6.0088x; 1.2086x over previous
#include <cuda_runtime.h>
#include <cuda_bf16.h>
#include <cstdint>
#include <math.h>

#define CC   256
#define HWD  4096
#define NB   2

using bf16 = __nv_bfloat16;

// ------------------------------ scratch -------------------------------------
__device__ __align__(1024) float d_bsf [NB * CC * HWD];            // [b][c][hw] fp32
__device__ __align__(1024) bf16  d_bsfT[NB * HWD * CC];            // [b][hw][c]
__device__ __align__(1024) bf16  d_Wb  [4 * CC * CC];              // theta,phi,g,out
__device__ __align__(1024) float d_bias2[2 * CC];                  // t_b || p_b
__device__ __align__(1024) bf16  d_TP  [NB * HWD * 2 * CC];        // [b][q][theta|phi]
__device__ __align__(1024) bf16  d_GB  [NB * CC * HWD];            // [b][c][k]
__device__ __align__(1024) bf16  d_SB  [(size_t)NB * HWD * HWD];   // [b][q][k]
__device__ __align__(1024) bf16  d_Yb  [NB * HWD * CC];            // [b][q][c]
__device__ __align__(1024) float d_OB  [NB * CC * HWD];            // [b][c][hw] fp32

// ------------------------------ helpers -------------------------------------
__device__ __forceinline__ uint32_t s2u(const void* p) {
    uint32_t a;
    asm("{ .reg .u64 t; cvta.to.shared.u64 t, %1; cvt.u32.u64 %0, t; }"
        : "=r"(a) : "l"(p));
    return a;
}
__device__ __forceinline__ void cp16(uint32_t dst, const void* src) {
    asm volatile("cp.async.cg.shared.global [%0], [%1], 16;" :: "r"(dst), "l"(src));
}
#define CP_COMMIT() asm volatile("cp.async.commit_group;" ::: "memory")

__device__ __forceinline__ void ldsm4(uint32_t& r0, uint32_t& r1,
                                      uint32_t& r2, uint32_t& r3, uint32_t a) {
    asm volatile("ldmatrix.sync.aligned.m8n8.x4.shared.b16 {%0,%1,%2,%3}, [%4];"
                 : "=r"(r0), "=r"(r1), "=r"(r2), "=r"(r3) : "r"(a));
}
__device__ __forceinline__ void mma16816(float* c, const uint32_t* a,
                                         uint32_t b0, uint32_t b1) {
    asm volatile(
        "mma.sync.aligned.m16n8k16.row.col.f32.bf16.bf16.f32 "
        "{%0,%1,%2,%3}, {%4,%5,%6,%7}, {%8,%9}, {%0,%1,%2,%3};"
        : "+f"(c[0]), "+f"(c[1]), "+f"(c[2]), "+f"(c[3])
        : "r"(a[0]), "r"(a[1]), "r"(a[2]), "r"(a[3]), "r"(b0), "r"(b1));
}

// ------------------------- bf16 TN GEMM (mma.sync) ---------------------------
// C[M,N] = A[M,K] * B[N,K]^T, A/B bf16 K-major. Block 128x128xK32, 256 thr.
// MODE 0: bf16 C, bias2[col]        (theta|phi fused)
// MODE 1: bf16 C, bias[row]         (g)
// MODE 2: bf16 C, no bias           (scores, y)
// MODE 3: fp32 C, bias[row] + bsf   (out conv)
#define ROWB   80
#define STAGEB (128 * ROWB)              // 10240 B per operand per stage
#define NSTAGE 4
#define GEMM_SMEM (NSTAGE * 2 * STAGEB)  // 81920

template<int MODE, int K>
__global__ __launch_bounds__(256, 2)
void k_gemm(const bf16* __restrict__ Ag, const bf16* __restrict__ Bg,
            void* __restrict__ Cg, int ldA, int ldB, int ldC,
            long long strA, long long strB, long long strC,
            const float* __restrict__ bias,
            const float* __restrict__ bsf, long long strBsf) {
    extern __shared__ char sm[];
    const int tid = threadIdx.x;
    const int wid = tid >> 5, lane = tid & 31;
    const int bz = blockIdx.z;
    const int n0 = blockIdx.x * 128, m0 = blockIdx.y * 128;
    const char* Ab = (const char*)(Ag + (size_t)bz * strA + (size_t)m0 * ldA);
    const char* Bb = (const char*)(Bg + (size_t)bz * strB + (size_t)n0 * ldB);
    const uint32_t sbase = s2u(sm);
    const int warpM = wid & 3, warpN = wid >> 2;
    const long lA2 = (long)ldA * 2, lB2 = (long)ldB * 2;

    float acc[2][8][4];
#pragma unroll
    for (int mt = 0; mt < 2; ++mt)
#pragma unroll
        for (int nt = 0; nt < 8; ++nt)
#pragma unroll
            for (int e = 0; e < 4; ++e) acc[mt][nt][e] = 0.f;

    constexpr int KT = K >> 5;

    auto load_stage = [&](int kt, int slot) {
        uint32_t dA = sbase + slot * (2 * STAGEB);
        uint32_t dB = dA + STAGEB;
        long koff = (long)kt * 64;
#pragma unroll
        for (int rep = 0; rep < 2; ++rep) {
            int task = rep * 256 + tid;       // 0..511
            int row = task >> 2, ch = task & 3;
            cp16(dA + row * ROWB + ch * 16, Ab + (long)row * lA2 + koff + ch * 16);
            cp16(dB + row * ROWB + ch * 16, Bb + (long)row * lB2 + koff + ch * 16);
        }
    };

    auto compute = [&](int slot) {
        uint32_t bA = sbase + slot * (2 * STAGEB);
        uint32_t bB = bA + STAGEB;
#pragma unroll
        for (int ks = 0; ks < 2; ++ks) {
            uint32_t a[2][4];
#pragma unroll
            for (int mt = 0; mt < 2; ++mt) {
                int row = warpM * 32 + mt * 16 + (lane & 15);
                ldsm4(a[mt][0], a[mt][1], a[mt][2], a[mt][3],
                      bA + row * ROWB + ks * 32 + ((lane >> 4) << 4));
            }
#pragma unroll
            for (int np = 0; np < 4; ++np) {
                int nrow = warpN * 64 + np * 16 + (lane & 7) + ((lane >> 4) << 3);
                uint32_t b0, b1, b2, b3;
                ldsm4(b0, b1, b2, b3,
                      bB + nrow * ROWB + ks * 32 + (((lane >> 3) & 1) << 4));
#pragma unroll
                for (int mt = 0; mt < 2; ++mt) {
                    mma16816(acc[mt][np * 2 + 0], a[mt], b0, b1);
                    mma16816(acc[mt][np * 2 + 1], a[mt], b2, b3);
                }
            }
        }
    };

    // prologue: fill NSTAGE-1 stages
#pragma unroll
    for (int s = 0; s < NSTAGE - 1; ++s) {
        if (s < KT) load_stage(s, s);
        CP_COMMIT();
    }
    // mainloop: one barrier per K32 iter; prefetch after the barrier targets
    // the slot all warps finished computing last iteration.
#pragma unroll 4
    for (int kt = 0; kt < KT; ++kt) {
        asm volatile("cp.async.wait_group %0;" :: "n"(NSTAGE - 2) : "memory");
        __syncthreads();
        compute(kt % NSTAGE);
        int j = kt + NSTAGE - 1;
        if (j < KT) load_stage(j, j % NSTAGE);
        CP_COMMIT();
    }

    // ---------------- epilogue ----------------
    const int mrow = m0 + warpM * 32 + (lane >> 2);
    const int ncol = n0 + warpN * 64 + ((lane & 3) << 1);
#pragma unroll
    for (int mt = 0; mt < 2; ++mt) {
        int r = mrow + mt * 16;
        float br0 = 0.f, br8 = 0.f;
        if (MODE == 1 || MODE == 3) { br0 = bias[r]; br8 = bias[r + 8]; }
#pragma unroll
        for (int nt = 0; nt < 8; ++nt) {
            int c = ncol + nt * 8;
            float v0 = acc[mt][nt][0], v1 = acc[mt][nt][1];
            float v2 = acc[mt][nt][2], v3 = acc[mt][nt][3];
            if (MODE == 0) {
                float bc0 = bias[c], bc1 = bias[c + 1];
                v0 += bc0; v1 += bc1; v2 += bc0; v3 += bc1;
            } else if (MODE == 1) {
                v0 += br0; v1 += br0; v2 += br8; v3 += br8;
            }
            if (MODE == 3) {
                float* C = (float*)Cg + (size_t)bz * strC;
                const float* bs = bsf + (size_t)bz * strBsf;
                float2 lo = *(const float2*)(bs + (size_t)r * ldC + c);
                float2 hi = *(const float2*)(bs + (size_t)(r + 8) * ldC + c);
                *(float2*)(C + (size_t)r * ldC + c) =
                    make_float2(v0 + br0 + lo.x, v1 + br0 + lo.y);
                *(float2*)(C + (size_t)(r + 8) * ldC + c) =
                    make_float2(v2 + br8 + hi.x, v3 + br8 + hi.y);
            } else {
                bf16* C = (bf16*)Cg + (size_t)bz * strC;
                *(__nv_bfloat162*)(C + (size_t)r * ldC + c) =
                    __floats2bfloat162_rn(v0, v1);
                *(__nv_bfloat162*)(C + (size_t)(r + 8) * ldC + c) =
                    __floats2bfloat162_rn(v2, v3);
            }
        }
    }
}

// ---------------------------- elementwise ------------------------------------
__global__ void k_wcvt(const float* __restrict__ tw, const float* __restrict__ pw,
                       const float* __restrict__ gw, const float* __restrict__ ow,
                       const float* __restrict__ tb, const float* __restrict__ pb) {
    int i = blockIdx.x * blockDim.x + threadIdx.x;
    if (i >= CC * CC) return;
    d_Wb[0 * CC * CC + i] = __float2bfloat16(tw[i]);
    d_Wb[1 * CC * CC + i] = __float2bfloat16(pw[i]);
    d_Wb[2 * CC * CC + i] = __float2bfloat16(gw[i]);
    d_Wb[3 * CC * CC + i] = __float2bfloat16(ow[i]);
    if (i < CC) { d_bias2[i] = tb[i]; d_bias2[CC + i] = pb[i]; }
}

// gather + dual-layout store: bsf fp32 [c][hw] and bf16 [hw][c]
__global__ void k_bsf_tr(const float* __restrict__ x0, const float* __restrict__ x1,
                         const float* __restrict__ x2, const float* __restrict__ x3) {
    __shared__ float t[32][33];
    int b = blockIdx.z;
    int hw0 = blockIdx.x * 32, c0 = blockIdx.y * 32;
    int tx = threadIdx.x;
    for (int i = threadIdx.y; i < 32; i += 8) {
        int c = c0 + i, hw = hw0 + tx;
        int nc = b * CC + c;
        int xq = hw & 63, yq = hw >> 6;
        const float* p0 = x0 + (size_t)nc * 128 * 128;
        int y2 = yq * 2, x2i = xq * 2;
        float m = fmaxf(fmaxf(p0[y2 * 128 + x2i],       p0[y2 * 128 + x2i + 1]),
                        fmaxf(p0[(y2 + 1) * 128 + x2i], p0[(y2 + 1) * 128 + x2i + 1]));
        float f1 = x1[(size_t)nc * 4096 + hw];
        float f2 = x2[(size_t)nc * 1024 + (yq >> 1) * 32 + (xq >> 1)];
        float f3 = x3[(size_t)nc * 256  + (yq >> 2) * 16 + (xq >> 2)];
        float v = 0.25f * (m + f1 + f2 + f3);
        d_bsf[(size_t)nc * HWD + hw] = v;
        t[i][tx] = v;
    }
    __syncthreads();
    for (int i = threadIdx.y; i < 32; i += 8)
        d_bsfT[((long)b * HWD + hw0 + i) * CC + c0 + tx] =
            __float2bfloat16(t[tx][i]);
}

__global__ void k_softmax() {                // in-place bf16 row softmax
    size_t r = blockIdx.x;
    uint32_t* row = (uint32_t*)(d_SB + r * HWD);    // 2048 u32 (bf16x2)
    int t = threadIdx.x;
    float v[16];
    float mx = -3.4e38f;
#pragma unroll
    for (int i = 0; i < 8; ++i) {
        uint32_t u = row[i * 256 + t];
        __nv_bfloat162 h = *(__nv_bfloat162*)&u;
        v[2 * i]     = __bfloat162float(h.x);
        v[2 * i + 1] = __bfloat162float(h.y);
        mx = fmaxf(mx, fmaxf(v[2 * i], v[2 * i + 1]));
    }
    __shared__ float red[256];
    red[t] = mx; __syncthreads();
    for (int s = 128; s > 0; s >>= 1) {
        if (t < s) red[t] = fmaxf(red[t], red[t + s]);
        __syncthreads();
    }
    mx = red[0]; __syncthreads();
    float sum = 0.f;
#pragma unroll
    for (int i = 0; i < 16; ++i) { v[i] = expf(v[i] - mx); sum += v[i]; }
    red[t] = sum; __syncthreads();
    for (int s = 128; s > 0; s >>= 1) {
        if (t < s) red[t] += red[t + s];
        __syncthreads();
    }
    float inv = 1.f / red[0];
#pragma unroll
    for (int i = 0; i < 8; ++i) {
        __nv_bfloat162 h = __floats2bfloat162_rn(v[2 * i] * inv, v[2 * i + 1] * inv);
        row[i * 256 + t] = *(uint32_t*)&h;
    }
}

__global__ void k_out0(const float* __restrict__ x0, float* __restrict__ out) {
    int idx = blockIdx.x * blockDim.x + threadIdx.x;
    if (idx >= NB * CC * 128 * 128) return;
    int x = idx & 127, y = (idx >> 7) & 127, nc = idx >> 14;
    out[idx] = d_OB[(size_t)nc * 4096 + (y >> 1) * 64 + (x >> 1)] + x0[idx];
}
__global__ void k_out1(const float* __restrict__ x1, float* __restrict__ out) {
    int idx = blockIdx.x * blockDim.x + threadIdx.x;
    if (idx >= NB * CC * HWD) return;
    out[idx] = d_OB[idx] + x1[idx];
}
__global__ void k_out2(const float* __restrict__ x2, float* __restrict__ out) {
    int idx = blockIdx.x * blockDim.x + threadIdx.x;
    if (idx >= NB * CC * 1024) return;
    int x = idx & 31, y = (idx >> 5) & 31, nc = idx >> 10;
    const float* p = d_OB + (size_t)nc * 4096 + (y * 2) * 64 + x * 2;
    float m = fmaxf(fmaxf(p[0], p[1]), fmaxf(p[64], p[65]));
    out[idx] = m + x2[idx];
}
__global__ void k_out3(const float* __restrict__ x3, float* __restrict__ out) {
    int idx = blockIdx.x * blockDim.x + threadIdx.x;
    if (idx >= NB * CC * 256) return;
    int x = idx & 15, y = (idx >> 4) & 15, nc = idx >> 8;
    const float* p = d_OB + (size_t)nc * 4096 + (y * 4) * 64 + x * 4;
    float m = -3.4e38f;
#pragma unroll
    for (int r = 0; r < 4; ++r)
#pragma unroll
        for (int c = 0; c < 4; ++c) m = fmaxf(m, p[r * 64 + c]);
    out[idx] = m + x3[idx];
}

// ------------------------------ launch ---------------------------------------
extern "C" void kernel_launch(void* const* d_in, const int* in_sizes, int n_in,
                              void* d_out, int out_size) {
    const float* x0 = (const float*)d_in[0];
    const float* x1 = (const float*)d_in[1];
    const float* x2 = (const float*)d_in[2];
    const float* x3 = (const float*)d_in[3];
    const float* g_w = (const float*)d_in[4];
    const float* g_b = (const float*)d_in[5];
    const float* t_w = (const float*)d_in[6];
    const float* t_b = (const float*)d_in[7];
    const float* p_w = (const float*)d_in[8];
    const float* p_b = (const float*)d_in[9];
    const float* o_w = (const float*)d_in[10];
    const float* o_b = (const float*)d_in[11];
    float* out = (float*)d_out;

    cudaFuncSetAttribute(k_gemm<0, 256>,  cudaFuncAttributeMaxDynamicSharedMemorySize, GEMM_SMEM);
    cudaFuncSetAttribute(k_gemm<1, 256>,  cudaFuncAttributeMaxDynamicSharedMemorySize, GEMM_SMEM);
    cudaFuncSetAttribute(k_gemm<2, 256>,  cudaFuncAttributeMaxDynamicSharedMemorySize, GEMM_SMEM);
    cudaFuncSetAttribute(k_gemm<2, 4096>, cudaFuncAttributeMaxDynamicSharedMemorySize, GEMM_SMEM);
    cudaFuncSetAttribute(k_gemm<3, 256>,  cudaFuncAttributeMaxDynamicSharedMemorySize, GEMM_SMEM);

    bf16* ptrW;  cudaGetSymbolAddress((void**)&ptrW,  d_Wb);
    bf16* ptrBT; cudaGetSymbolAddress((void**)&ptrBT, d_bsfT);
    bf16* ptrTP; cudaGetSymbolAddress((void**)&ptrTP, d_TP);
    bf16* ptrG;  cudaGetSymbolAddress((void**)&ptrG,  d_GB);
    bf16* ptrS;  cudaGetSymbolAddress((void**)&ptrS,  d_SB);
    bf16* ptrY;  cudaGetSymbolAddress((void**)&ptrY,  d_Yb);
    float* ptrB; cudaGetSymbolAddress((void**)&ptrB,  d_bsf);
    float* ptrO; cudaGetSymbolAddress((void**)&ptrO,  d_OB);
    float* ptrB2; cudaGetSymbolAddress((void**)&ptrB2, d_bias2);

    k_wcvt<<<(CC * CC + 255) / 256, 256>>>(t_w, p_w, g_w, o_w, t_b, p_b);
    {
        dim3 g(HWD / 32, CC / 32, NB);
        k_bsf_tr<<<g, dim3(32, 8)>>>(x0, x1, x2, x3);
    }
    // theta|phi fused: C[q][0:512] = bsfT * [Wt;Wp]^T  (N=512)
    {
        dim3 g(2 * CC / 128, HWD / 128, NB);
        k_gemm<0, 256><<<g, 256, GEMM_SMEM>>>(ptrBT, ptrW, ptrTP,
                                              CC, CC, 2 * CC,
                                              (long long)HWD * CC, 0,
                                              (long long)HWD * 2 * CC,
                                              ptrB2, nullptr, 0);
    }
    // g: C[co][k] = Wg * bsfT^T
    {
        dim3 g(HWD / 128, CC / 128, NB);
        k_gemm<1, 256><<<g, 256, GEMM_SMEM>>>(ptrW + 2 * CC * CC, ptrBT, ptrG,
                                              CC, CC, HWD,
                                              0, (long long)HWD * CC,
                                              (long long)CC * HWD,
                                              g_b, nullptr, 0);
    }
    // scores: C[q][k] = theta * phi^T   (A/B interleaved in d_TP, ld 512)
    {
        dim3 g(HWD / 128, HWD / 128, NB);
        k_gemm<2, 256><<<g, 256, GEMM_SMEM>>>(ptrTP, ptrTP + CC, ptrS,
                                              2 * CC, 2 * CC, HWD,
                                              (long long)HWD * 2 * CC,
                                              (long long)HWD * 2 * CC,
                                              (long long)HWD * HWD,
                                              nullptr, nullptr, 0);
    }
    k_softmax<<<NB * HWD, 256>>>();
    // y: C[q][c] = SB * GB^T
    {
        dim3 g(CC / 128, HWD / 128, NB);
        k_gemm<2, 4096><<<g, 256, GEMM_SMEM>>>(ptrS, ptrG, ptrY,
                                               HWD, HWD, CC,
                                               (long long)HWD * HWD,
                                               (long long)CC * HWD,
                                               (long long)HWD * CC,
                                               nullptr, nullptr, 0);
    }
    // out conv: C[co][q] = Wo * Yb^T + bias + bsf
    {
        dim3 g(HWD / 128, CC / 128, NB);
        k_gemm<3, 256><<<g, 256, GEMM_SMEM>>>(ptrW + 3 * CC * CC, ptrY, ptrO,
                                              CC, CC, HWD,
                                              0, (long long)HWD * CC,
                                              (long long)CC * HWD,
                                              o_b, ptrB, (long long)CC * HWD);
    }
    float* o0 = out;
    float* o1 = o0 + (size_t)NB * CC * 128 * 128;
    float* o2 = o1 + (size_t)NB * CC * 64 * 64;
    float* o3 = o2 + (size_t)NB * CC * 32 * 32;
    k_out0<<<(NB * CC * 128 * 128 + 255) / 256, 256>>>(x0, o0);
    k_out1<<<(NB * CC * HWD + 255) / 256, 256>>>(x1, o1);
    k_out2<<<(NB * CC * 1024 + 255) / 256, 256>>>(x2, o2);
    k_out3<<<(NB * CC * 256 + 255) / 256, 256>>>(x3, o3);
}